// round 15
// baseline (speedup 1.0000x reference)
#include <cuda_runtime.h>
#include <cuda_fp16.h>
#include <cstdint>

#define TT 256
#define HH 512
#define BB 128
#define NGATE 2048
#define GRID 128
#define NTHR 512
#define NKC 8
#define RSH 144                 // halves per padded row (288 B; 288%128=32 -> conflict-free)
#define CH_HF (128*RSH)         // halves per full 128-row chunk (18432)
#define STG_BY 18432            // bytes per smem stage
#define SMEMB 147456            // 8 stages -> whole cell resident, no recycling

#define O_H1F 16777216L
#define O_M0  16908288L
#define O_M1F 33685504L

// ---------------- device scratch ----------------
// W fp16 fragment order, float4 index fi4 = [cell(2)][n0b(5)][kc(3)][wn4(2)][ks(3)][lane(5)],
// halves within float4: j(1) r(1) hb(1)
__device__ __align__(16) __half g_Wf[8388608L];
__device__ __align__(16) float g_bias[4][NGATE];
// chunk-major padded fp16 A sources: [kc][m(128)][144]
__device__ __align__(16) __half g_H0r[(long)TT*4*CH_HF];
__device__ __align__(16) __half g_h1r[2][2][4*CH_HF];   // [layer][parity]
__device__ __align__(16) __half g_h0ar[4*CH_HF];
__device__ __align__(16) __half g_h0br[4*CH_HF];
// linear full-precision state
__device__ __align__(16) float g_h1f[2][BB*HH];
__device__ __align__(16) float g_m1[2][BB*HH];
__device__ __align__(16) float g_m0a[BB*HH];
__device__ unsigned g_cnt;
__device__ volatile unsigned g_gen;

// ---------------- helpers ----------------
__device__ __forceinline__ float sigf(float x) {
    return __fdividef(1.f, 1.f + __expf(-x));
}
__device__ __forceinline__ float tanhfast(float x) {
    return 1.f - __fdividef(2.f, __expf(2.f * x) + 1.f);
}

// fp16 mma: D(16x8) += A(16x16) B(16x8), fp32 accum
__device__ __forceinline__ void mma16(float* c, unsigned a0, unsigned a1, unsigned a2, unsigned a3,
                                      unsigned b0, unsigned b1) {
    asm volatile(
        "mma.sync.aligned.m16n8k16.row.col.f32.f16.f16.f32 "
        "{%0,%1,%2,%3}, {%4,%5,%6,%7}, {%8,%9}, {%0,%1,%2,%3};"
        : "+f"(c[0]), "+f"(c[1]), "+f"(c[2]), "+f"(c[3])
        : "r"(a0), "r"(a1), "r"(a2), "r"(a3), "r"(b0), "r"(b1));
}

__device__ __forceinline__ void mbwait(uint32_t mbar, unsigned par) {
    asm volatile(
        "{\n\t.reg .pred P;\n\t"
        "W%=:\n\t"
        "mbarrier.try_wait.parity.shared.b64 P, [%0], %1;\n\t"
        "@!P bra W%=;\n\t}"
        :: "r"(mbar), "r"(par) : "memory");
}

// one bulk copy: 64 rows x 144 halves (18432 B) -> smem stage (tid 0 only)
__device__ __forceinline__ void ldbulk(uint32_t sb, uint32_t mb0, int st, int kc,
                                       const __half* xq, const __half* hq)
{
    const __half* src = (kc < 4) ? (xq + (long)kc * CH_HF) : (hq + (long)(kc - 4) * CH_HF);
    uint32_t dst = sb + (uint32_t)st * STG_BY;
    uint32_t mb = mb0 + st * 8;
    asm volatile("mbarrier.arrive.expect_tx.shared.b64 _, [%0], %1;"
                 :: "r"(mb), "r"(STG_BY) : "memory");
    asm volatile("cp.async.bulk.shared::cluster.global.mbarrier::complete_tx::bytes "
                 "[%0], [%1], %2, [%3];"
                 :: "r"(dst), "l"(src), "r"(STG_BY), "r"(mb) : "memory");
}

// grid barrier (R9-proven atomic form): 128 CTAs, all resident -> deadlock-free
__device__ __forceinline__ void gsync() {
    __threadfence();
    __syncthreads();
    if (threadIdx.x == 0) {
        unsigned g = g_gen;
        if (atomicAdd(&g_cnt, 1u) == GRID - 1) {
            g_cnt = 0;
            __threadfence();
            g_gen = g + 1;
        } else {
            while (g_gen == g) { }
        }
    }
    __syncthreads();
    __threadfence();
}

// permuted half-offset within a slab for original k-feature u (0..511)
__device__ __forceinline__ long kpos(int u) {
    int kc2 = u >> 7, k2 = u & 127;
    int blk = k2 >> 4, kb = (k2 >> 1) & 7, hb = k2 & 1;
    int p = (kb < 4) ? (2 * kb) : (2 * (kb - 4) + 1);
    return (long)kc2 * CH_HF + blk * 16 + p * 2 + hb;
}

// one LSTM cell tile: gates[64 x 64] = [x;h] @ W^T + b, then elementwise.
// 16 warps, warp tile 16m x 16n, fp16 operands, fp32 accum.
// ZERO intra-cell __syncthreads: all 8 bulk copies issued up front into
// dedicated stages; the only waits are per-chunk mbarriers.
__device__ __noinline__ void cell_run(uint32_t sb, char* smc, uint32_t mb0, unsigned* mpar,
    int n0,
    const __half* xq, const __half* hq,
    const float* bias_n0,
    const float* cold,
    float* hfull, long hfs, __half* hrd, float* cdst, long cds,
    const float4* wbase)
{
    int tid = threadIdx.x, w = tid >> 5, lane = tid & 31;
    int rb = lane >> 2, q = lane & 3;
    int wm = (w & 3) * 16;
    int wn4 = w >> 2;
    int wn = wn4 * 16;

    float acc[2][4];
    #pragma unroll
    for (int j = 0; j < 2; ++j)
        #pragma unroll
        for (int v = 0; v < 4; ++v) acc[j][v] = 0.f;

    float4 bA[4], bB[4];
    const float4* wl = wbase + wn4 * 256 + lane;

    // W loader: half h_ (4 k-steps) of chunk kc -> buf (4 x LDG.128)
    #define LOADB(buf, kc_, h_) do {                                           \
        const float4* wp_ = wl + (kc_) * 1024 + (h_) * 128;                    \
        _Pragma("unroll")                                                      \
        for (int s_ = 0; s_ < 4; ++s_)                                         \
            (buf)[s_] = wp_[s_ * 32];                                          \
    } while (0)

    // compute 4 k-steps (64 k) from A stage + reg W buf
    #define COMP4(buf, Ab_, qr_) do {                                          \
        const char* ap_ = (Ab_) + (wm + rb) * 288 + 8 * q + (qr_) * 128;       \
        _Pragma("unroll")                                                      \
        for (int s_ = 0; s_ < 4; ++s_) {                                       \
            uint2 lo_ = *(const uint2*)(ap_ + s_ * 32);                        \
            uint2 hi_ = *(const uint2*)(ap_ + 8 * 288 + s_ * 32);              \
            float4 bv_ = (buf)[s_];                                            \
            mma16(acc[0], lo_.x, hi_.x, lo_.y, hi_.y,                          \
                  __float_as_uint(bv_.x), __float_as_uint(bv_.y));             \
            mma16(acc[1], lo_.x, hi_.x, lo_.y, hi_.y,                          \
                  __float_as_uint(bv_.z), __float_as_uint(bv_.w));             \
        }                                                                      \
    } while (0)

    if (tid == 0) {
        #pragma unroll
        for (int kc = 0; kc < NKC; ++kc)
            ldbulk(sb, mb0, kc, kc, xq, hq);
    }
    LOADB(bA, 0, 0);

    #pragma unroll 1
    for (int kc = 0; kc < NKC; ++kc) {
        mbwait(mb0 + kc * 8, mpar[kc] & 1);      // chunk kc data landed
        mpar[kc]++;

        char* Ab = smc + kc * STG_BY;
        LOADB(bB, kc, 1);                        // prefetch 2nd half of this chunk's W
        COMP4(bA, Ab, 0);
        if (kc + 1 < NKC) LOADB(bA, kc + 1, 0);  // prefetch 1st half of next chunk's W
        COMP4(bB, Ab, 1);
    }
    #undef LOADB
    #undef COMP4

    // elementwise LSTM, both-lane version (no idle lanes).
    bool ev = !(q & 1);
    #pragma unroll
    for (int j = 0; j < 2; ++j) {
        int lb = wn + 8 * j + ((q >> 1) << 2);      // unit base col (local), mult of 4
        float4 bb = *(const float4*)(bias_n0 + lb); // (b_i, b_f, b_g, b_o)
        float s0 = ev ? acc[j][2] : acc[j][0];
        float s1 = ev ? acc[j][3] : acc[j][1];
        float p0 = __shfl_xor_sync(0xffffffffu, s0, 1);
        float p1 = __shfl_xor_sync(0xffffffffu, s1, 1);
        float ig = (ev ? acc[j][0] : p0) + bb.x;
        float fg = (ev ? acc[j][1] : p1) + bb.y;
        float gg = (ev ? p0 : acc[j][2]) + bb.z;
        float og = (ev ? p1 : acc[j][3]) + bb.w;
        int mrow = wm + rb + (ev ? 0 : 8);          // 0..63 local
        int u = (n0 + lb) >> 2;                     // global unit 0..511
        float co = cold ? __ldcg(cold + (long)mrow * HH + u) : 0.f;
        float cn = sigf(fg) * co + sigf(ig) * tanhfast(gg);
        float hn = sigf(og) * tanhfast(cn);
        if (hfull) hfull[(long)mrow * hfs + u] = hn;
        hrd[kpos(u) + (long)mrow * RSH] = __float2half_rn(hn);
        cdst[(long)mrow * cds + u] = cn;
    }
}

// ---------------- main persistent kernel ----------------
__global__ void __launch_bounds__(NTHR, 1) lstm_main(float* __restrict__ out) {
    extern __shared__ __align__(16) char smc[];
    __shared__ __align__(8) unsigned long long s_mbar[8];
    uint32_t sb = (uint32_t)__cvta_generic_to_shared(smc);
    uint32_t mb0 = (uint32_t)__cvta_generic_to_shared(&s_mbar[0]);

    int tid = threadIdx.x;
    int cta = blockIdx.x;
    int grp = cta >> 6;
    int c = cta & 63;
    int m0 = (c & 1) * 64;
    int n0b = c >> 1;
    int n0 = n0b * 64;
    const long TH = (long)TT * HH;
    long moS = (long)m0 * RSH;       // half-slab offset
    long moH = (long)m0 * HH;
    long moT = (long)m0 * TH;

    if (tid == 0) {
        #pragma unroll
        for (int s = 0; s < 8; ++s)
            asm volatile("mbarrier.init.shared.b64 [%0], 1;" :: "r"(mb0 + s * 8) : "memory");
    }
    __syncthreads();

    unsigned mpar[8] = {0, 0, 0, 0, 0, 0, 0, 0};

    const float4* w0 = (const float4*)g_Wf + ((long)(0 * 32 + n0b)) * 8192;
    const float4* w1 = (const float4*)g_Wf + ((long)(1 * 32 + n0b)) * 8192;
    const float4* w2 = (const float4*)g_Wf + ((long)(2 * 32 + n0b)) * 8192;
    const float4* w3 = (const float4*)g_Wf + ((long)(3 * 32 + n0b)) * 8192;

    #pragma unroll 1
    for (int ph = 0; ph <= 2 * TT; ++ph) {
        int t = ph >> 1;
        if (!(ph & 1)) {
            if (grp == 0) {
                if (t < TT)   // cell00(t): x=h1r[0][t&1], h=H0r[:,t], c=0 -> h0ar,m0a
                    cell_run(sb, smc, mb0, mpar, n0,
                             g_h1r[0][t & 1] + moS,
                             g_H0r + (long)t * 4 * CH_HF + moS,
                             &g_bias[0][n0], nullptr,
                             nullptr, 0, g_h0ar + moS, g_m0a + moH, HH, w0);
            } else if (t >= 1) {  // cell11(t-1): x=h0br, h=h1r[1], c=m1[1]
                int tp = t - 1;
                cell_run(sb, smc, mb0, mpar, n0,
                         g_h0br + moS, g_h1r[1][tp & 1] + moS,
                         &g_bias[3][n0], g_m1[1] + moH,
                         g_h1f[1] + moH, HH, g_h1r[1][(tp + 1) & 1] + moS,
                         g_m1[1] + moH, HH, w3);
            }
        } else {
            if (grp == 0) {       // cell01(t): x=h0ar, h=h1r[0], c=m1[0]
                cell_run(sb, smc, mb0, mpar, n0,
                         g_h0ar + moS, g_h1r[0][t & 1] + moS,
                         &g_bias[1][n0], g_m1[0] + moH,
                         g_h1f[0] + moH, HH, g_h1r[0][(t + 1) & 1] + moS,
                         g_m1[0] + moH, HH, w1);
            } else {              // cell10(t): x=h1r[1], h=h0ar, c=m0a -> d_out + h0br
                cell_run(sb, smc, mb0, mpar, n0,
                         g_h1r[1][t & 1] + moS, g_h0ar + moS,
                         &g_bias[2][n0], g_m0a + moH,
                         out + moT + (long)t * HH, TH, g_h0br + moS,
                         out + O_M0 + moT + (long)t * HH, TH, w2);
            }
        }
        gsync();
    }

    // final H1f / M1f
    for (long idx = (long)cta * NTHR + tid; idx < 2L * BB * HH; idx += (long)GRID * NTHR) {
        int b = (int)(idx >> 10), l = (int)((idx >> 9) & 1), j = (int)(idx & 511);
        out[O_H1F + idx] = __ldcg(&g_h1f[l][b * HH + j]);
        out[O_M1F + idx] = __ldcg(&g_m1[l][b * HH + j]);
    }
}

// ---------------- prep kernels ----------------
// W fp16 fragment order. Half index f bits (LSB up):
// hb(1) r(1) j(1) lane(5) ks(3) wn4(2) kc(3) n0b(5) cell(2)
__global__ void prep_wf(const float* __restrict__ Wih, const float* __restrict__ Whh) {
    long f = (long)blockIdx.x * blockDim.x + threadIdx.x;
    if (f >= 8388608L) return;
    int hb   = (int)(f & 1);
    int r    = (int)((f >> 1) & 1);
    int j    = (int)((f >> 2) & 1);
    int lane = (int)((f >> 3) & 31);
    int ks   = (int)((f >> 8) & 7);
    int wn4  = (int)((f >> 11) & 3);
    int kc   = (int)((f >> 13) & 7);
    int n0b  = (int)((f >> 16) & 31);
    int cell = (int)(f >> 21);
    int rb = lane >> 2, q = lane & 3;
    int row = n0b * 64 + wn4 * 16 + j * 8 + rb;      // gate-interleaved: row = 4*unit + gate
    int g = row & 3, uu = row >> 2;
    long srow = (long)cell * NGATE + g * HH + uu;
    int k = kc * 128 + ks * 16 + r * 8 + 2 * q + hb;  // original k index
    float v = (k < HH) ? Wih[srow * HH + k] : Whh[srow * HH + (k - HH)];
    g_Wf[f] = __float2half_rn(v);
}

// H0 [B][T][H] -> g_H0r [t][kc][m][144] fp16, pair-level FORWARD k-permute
__global__ void prep_x(const float* __restrict__ H0) {
    long i = (long)blockIdx.x * blockDim.x + threadIdx.x;
    if (i >= (long)BB * TT * HH) return;
    int h = (int)(i & 511);
    int t = (int)((i >> 9) & 255);
    int b = (int)(i >> 17);
    int kc = h >> 7, k2 = h & 127;
    int blk = k2 >> 4, kb = (k2 >> 1) & 7, hb = k2 & 1;
    int p = (kb < 4) ? (2 * kb) : (2 * (kb - 4) + 1);
    int col = blk * 16 + p * 2 + hb;
    g_H0r[((long)t * 4 + kc) * CH_HF + (long)b * RSH + col] = __float2half_rn(H0[i]);
}

__global__ void prep_misc(const float* __restrict__ bih, const float* __restrict__ bhh) {
    long i = (long)blockIdx.x * blockDim.x + threadIdx.x;
    if (i < 147456) ((int*)g_h1r)[i] = 0;                        // zero fp16 h1r slabs
    if (i < 2L * BB * HH) { ((float*)g_h1f)[i] = 0.f; ((float*)g_m1)[i] = 0.f; }
    if (i < 4 * NGATE) {
        int nr = (int)(i & 2047), cc = (int)(i >> 11);
        int g = nr & 3, j = nr >> 2;
        long s = (long)cc * NGATE + g * HH + j;
        ((float*)g_bias)[i] = bih[s] + bhh[s];
    }
    if (i == 0) { g_cnt = 0; g_gen = 0; }
}

// ---------------- launch ----------------
extern "C" void kernel_launch(void* const* d_in, const int* in_sizes, int n_in,
                              void* d_out, int out_size) {
    const float* H0  = (const float*)d_in[0];
    const float* Wih = (const float*)d_in[1];
    const float* Whh = (const float*)d_in[2];
    const float* bih = (const float*)d_in[3];
    const float* bhh = (const float*)d_in[4];
    float* out = (float*)d_out;

    prep_wf<<<32768, 256>>>(Wih, Whh);
    prep_x<<<65536, 256>>>(H0);
    prep_misc<<<1024, 256>>>(bih, bhh);

    cudaFuncSetAttribute(lstm_main, cudaFuncAttributeMaxDynamicSharedMemorySize, SMEMB);
    lstm_main<<<GRID, NTHR, SMEMB>>>(out);
}

// round 16
// speedup vs baseline: 1.2107x; 1.2107x over previous
#include <cuda_runtime.h>
#include <cuda_fp16.h>
#include <cstdint>

#define TT 256
#define HH 512
#define BB 128
#define NGATE 2048
#define GRID 128
#define NTHR 512
#define RSH 144                 // halves per padded row (288 B; 288%128=32 -> conflict-free)
#define CH_HF (128*RSH)         // halves per full 128-row chunk (18432)
#define STG_BY 18432            // bytes per smem stage
#define SMEMB 147456            // 8 dedicated stages (stage == kc)

#define O_H1F 16777216L
#define O_M0  16908288L
#define O_M1F 33685504L

// ---------------- device scratch ----------------
// W fp16 fragment order, float4 index fi4 = [cell(2)][n0b(5)][kc(3)][wn4(2)][ks(3)][lane(5)],
// halves within float4: j(1) r(1) hb(1)
__device__ __align__(16) __half g_Wf[8388608L];
__device__ __align__(16) float g_bias[4][NGATE];
// chunk-major padded fp16 A sources: [kc][m(128)][144]
__device__ __align__(16) __half g_H0r[(long)TT*4*CH_HF];
__device__ __align__(16) __half g_h1r[2][2][4*CH_HF];   // [layer][parity]
__device__ __align__(16) __half g_h0ar[4*CH_HF];
__device__ __align__(16) __half g_h0br[4*CH_HF];
// linear full-precision state
__device__ __align__(16) float g_h1f[2][BB*HH];
__device__ __align__(16) float g_m1[2][BB*HH];
__device__ __align__(16) float g_m0a[BB*HH];
__device__ unsigned g_cnt;
__device__ volatile unsigned g_gen;

// ---------------- helpers ----------------
__device__ __forceinline__ float sigf(float x) {
    return __fdividef(1.f, 1.f + __expf(-x));
}
__device__ __forceinline__ float tanhfast(float x) {
    return 1.f - __fdividef(2.f, __expf(2.f * x) + 1.f);
}

// fp16 mma: D(16x8) += A(16x16) B(16x8), fp32 accum
__device__ __forceinline__ void mma16(float* c, unsigned a0, unsigned a1, unsigned a2, unsigned a3,
                                      unsigned b0, unsigned b1) {
    asm volatile(
        "mma.sync.aligned.m16n8k16.row.col.f32.f16.f16.f32 "
        "{%0,%1,%2,%3}, {%4,%5,%6,%7}, {%8,%9}, {%0,%1,%2,%3};"
        : "+f"(c[0]), "+f"(c[1]), "+f"(c[2]), "+f"(c[3])
        : "r"(a0), "r"(a1), "r"(a2), "r"(a3), "r"(b0), "r"(b1));
}

__device__ __forceinline__ void mbwait(uint32_t mbar, unsigned par) {
    asm volatile(
        "{\n\t.reg .pred P;\n\t"
        "W%=:\n\t"
        "mbarrier.try_wait.parity.shared.b64 P, [%0], %1;\n\t"
        "@!P bra W%=;\n\t}"
        :: "r"(mbar), "r"(par) : "memory");
}

// issue 4 bulk copies: slab chunks 0-3 -> stages stg0..stg0+3 (tid 0 only, caller guards)
__device__ __forceinline__ void issue_half(uint32_t sb, uint32_t mb0, int stg0, const __half* slab) {
    #pragma unroll
    for (int i = 0; i < 4; ++i) {
        const __half* src = slab + (long)i * CH_HF;
        uint32_t dst = sb + (uint32_t)(stg0 + i) * STG_BY;
        uint32_t mb = mb0 + (stg0 + i) * 8;
        asm volatile("mbarrier.arrive.expect_tx.shared.b64 _, [%0], %1;"
                     :: "r"(mb), "r"(STG_BY) : "memory");
        asm volatile("cp.async.bulk.shared::cluster.global.mbarrier::complete_tx::bytes "
                     "[%0], [%1], %2, [%3];"
                     :: "r"(dst), "l"(src), "r"(STG_BY), "r"(mb) : "memory");
    }
}

// permuted half-offset within a slab for original k-feature u (0..511)
__device__ __forceinline__ long kpos(int u) {
    int kc2 = u >> 7, k2 = u & 127;
    int blk = k2 >> 4, kb = (k2 >> 1) & 7, hb = k2 & 1;
    int p = (kb < 4) ? (2 * kb) : (2 * (kb - 4) + 1);
    return (long)kc2 * CH_HF + blk * 16 + p * 2 + hb;
}

// W loader: half h_ (4 k-steps) of chunk kc -> buf (4 x LDG.128)
#define LOADB(buf, kc_, h_) do {                                           \
    const float4* wp_ = wl + (kc_) * 1024 + (h_) * 128;                    \
    _Pragma("unroll")                                                      \
    for (int s_ = 0; s_ < 4; ++s_)                                         \
        (buf)[s_] = wp_[s_ * 32];                                          \
} while (0)

// compute 4 k-steps (64 k) from A stage + reg W buf
#define COMP4(buf, Ab_, qr_) do {                                          \
    const char* ap_ = (Ab_) + (wm + rb) * 288 + 8 * q + (qr_) * 128;       \
    _Pragma("unroll")                                                      \
    for (int s_ = 0; s_ < 4; ++s_) {                                       \
        uint2 lo_ = *(const uint2*)(ap_ + s_ * 32);                        \
        uint2 hi_ = *(const uint2*)(ap_ + 8 * 288 + s_ * 32);              \
        float4 bv_ = (buf)[s_];                                            \
        mma16(acc[0], lo_.x, hi_.x, lo_.y, hi_.y,                          \
              __float_as_uint(bv_.x), __float_as_uint(bv_.y));             \
        mma16(acc[1], lo_.x, hi_.x, lo_.y, hi_.y,                          \
              __float_as_uint(bv_.z), __float_as_uint(bv_.w));             \
    }                                                                      \
} while (0)

// half-GEMM: 4 chunks at stages stg0..stg0+3 (stage == W kc), accumulate into acc
__device__ __forceinline__ void half_gemm(float (*acc)[4], char* smc, uint32_t mb0, unsigned* mpar,
                                          int stg0, const float4* wl, int wm, int rb, int q)
{
    float4 bA[4], bB[4];
    LOADB(bA, stg0, 0);
    #pragma unroll 1
    for (int i = 0; i < 4; ++i) {
        int st = stg0 + i;
        mbwait(mb0 + st * 8, mpar[st] & 1);
        mpar[st]++;
        char* Ab = smc + st * STG_BY;
        LOADB(bB, st, 1);
        COMP4(bA, Ab, 0);
        if (i < 3) LOADB(bA, st + 1, 0);
        COMP4(bB, Ab, 1);
    }
}

// ---------------- main persistent kernel ----------------
__global__ void __launch_bounds__(NTHR, 1) lstm_main(float* __restrict__ out) {
    extern __shared__ __align__(16) char smc[];
    __shared__ __align__(8) unsigned long long s_mbar[8];
    uint32_t sb = (uint32_t)__cvta_generic_to_shared(smc);
    uint32_t mb0 = (uint32_t)__cvta_generic_to_shared(&s_mbar[0]);

    int tid = threadIdx.x, w = tid >> 5, lane = tid & 31;
    int rb = lane >> 2, q = lane & 3;
    int wm = (w & 3) * 16;
    int wn4 = w >> 2;
    int wn = wn4 * 16;

    int cta = blockIdx.x;
    int grp = cta >> 6;
    int c = cta & 63;
    int m0 = (c & 1) * 64;
    int n0b = c >> 1;
    int n0 = n0b * 64;
    const long TH = (long)TT * HH;
    long moS = (long)m0 * RSH;
    long moH = (long)m0 * HH;
    long moT = (long)m0 * TH;

    if (tid == 0) {
        #pragma unroll
        for (int s = 0; s < 8; ++s)
            asm volatile("mbarrier.init.shared.b64 [%0], 1;" :: "r"(mb0 + s * 8) : "memory");
    }
    __syncthreads();

    unsigned mpar[8] = {0, 0, 0, 0, 0, 0, 0, 0};

    const float4* w0 = (const float4*)g_Wf + ((long)(0 * 32 + n0b)) * 8192;
    const float4* w1 = (const float4*)g_Wf + ((long)(1 * 32 + n0b)) * 8192;
    const float4* w2 = (const float4*)g_Wf + ((long)(2 * 32 + n0b)) * 8192;
    const float4* w3 = (const float4*)g_Wf + ((long)(3 * 32 + n0b)) * 8192;

    float acc[2][4];
    #pragma unroll
    for (int j = 0; j < 2; ++j)
        #pragma unroll
        for (int v = 0; v < 4; ++v) acc[j][v] = 0.f;
    bool have_early = false;

    #pragma unroll 1
    for (int ph = 0; ph <= 2 * TT; ++ph) {
        int t = ph >> 1;

        // ---- current cell descriptor ----
        const __half* xs = nullptr;   // late operand slab (x, kc 0-3)
        const __half* hs = nullptr;   // early operand slab (h, kc 4-7)
        const float* bias = nullptr;
        const float* cold = nullptr;
        float* hfull = nullptr; long hfs = 0;
        __half* hrd = nullptr;
        float* cdst = nullptr; long cds = 0;
        const float4* wb = nullptr;
        bool active = false;

        if (!(ph & 1)) {
            if (grp == 0) {
                if (t < TT) {          // cell00(t)
                    active = true;
                    xs = g_h1r[0][t & 1] + moS;
                    hs = g_H0r + (long)t * 4 * CH_HF + moS;
                    bias = &g_bias[0][n0]; cold = nullptr;
                    hfull = nullptr; hfs = 0;
                    hrd = g_h0ar + moS; cdst = g_m0a + moH; cds = HH;
                    wb = w0;
                }
            } else if (t >= 1) {       // cell11(t-1)
                int tp = t - 1;
                active = true;
                xs = g_h0br + moS;
                hs = g_h1r[1][tp & 1] + moS;
                bias = &g_bias[3][n0]; cold = g_m1[1] + moH;
                hfull = g_h1f[1] + moH; hfs = HH;
                hrd = g_h1r[1][(tp + 1) & 1] + moS; cdst = g_m1[1] + moH; cds = HH;
                wb = w3;
            }
        } else {
            if (grp == 0) {            // cell01(t)
                active = true;
                xs = g_h0ar + moS;
                hs = g_h1r[0][t & 1] + moS;
                bias = &g_bias[1][n0]; cold = g_m1[0] + moH;
                hfull = g_h1f[0] + moH; hfs = HH;
                hrd = g_h1r[0][(t + 1) & 1] + moS; cdst = g_m1[0] + moH; cds = HH;
                wb = w1;
            } else {                   // cell10(t) — both operands late
                active = true;
                xs = g_h1r[1][t & 1] + moS;
                hs = g_h0ar + moS;
                bias = &g_bias[2][n0]; cold = g_m0a + moH;
                hfull = out + moT + (long)t * HH; hfs = TH;
                hrd = g_h0br + moS; cdst = out + O_M0 + moT + (long)t * HH; cds = TH;
                wb = w2;
            }
        }

        // ---- phase body ----
        if (active) {
            const float4* wl = wb + wn4 * 256 + lane;
            if (tid == 0) {
                issue_half(sb, mb0, 0, xs);                    // late x chunks
                if (!have_early) issue_half(sb, mb0, 4, hs);   // h chunks (not prefetched)
            }
            half_gemm(acc, smc, mb0, mpar, 0, wl, wm, rb, q);  // x half
            if (!have_early)
                half_gemm(acc, smc, mb0, mpar, 4, wl, wm, rb, q);  // h half

            // ---- epilogue (both-lane, cheap activations) ----
            bool ev = !(q & 1);
            #pragma unroll
            for (int j = 0; j < 2; ++j) {
                int lb = wn + 8 * j + ((q >> 1) << 2);
                float4 bb = *(const float4*)(bias + lb);
                float s0 = ev ? acc[j][2] : acc[j][0];
                float s1 = ev ? acc[j][3] : acc[j][1];
                float p0 = __shfl_xor_sync(0xffffffffu, s0, 1);
                float p1 = __shfl_xor_sync(0xffffffffu, s1, 1);
                float ig = (ev ? acc[j][0] : p0) + bb.x;
                float fg = (ev ? acc[j][1] : p1) + bb.y;
                float gg = (ev ? p0 : acc[j][2]) + bb.z;
                float og = (ev ? p1 : acc[j][3]) + bb.w;
                int mrow = wm + rb + (ev ? 0 : 8);
                int u = (n0 + lb) >> 2;
                float co = cold ? __ldcg(cold + (long)mrow * HH + u) : 0.f;
                float cn = sigf(fg) * co + sigf(ig) * tanhfast(gg);
                float hn = sigf(og) * tanhfast(cn);
                if (hfull) hfull[(long)mrow * hfs + u] = hn;
                hrd[kpos(u) + (long)mrow * RSH] = __float2half_rn(hn);
                cdst[(long)mrow * cds + u] = cn;
            }
            #pragma unroll
            for (int j = 0; j < 2; ++j)
                #pragma unroll
                for (int v = 0; v < 4; ++v) acc[j][v] = 0.f;
        }

        // ---- arrive ----
        __threadfence();
        __syncthreads();
        if (tid == 0) {
            if (atomicAdd(&g_cnt, 1u) == GRID - 1) {
                g_cnt = 0;
                __threadfence();
                g_gen = (unsigned)(ph + 1);
            }
        }

        // ---- early work for next phase's cell (overlaps barrier wait) ----
        {
            int php = ph + 1;
            int tn = php >> 1;
            const __half* nhs = nullptr;
            const float4* nwb = nullptr;
            if (php <= 2 * TT) {
                if (!(php & 1)) {
                    if (grp == 0) { if (tn < TT) { nhs = g_H0r + (long)tn * 4 * CH_HF + moS; nwb = w0; } }
                    else if (tn >= 1) { nhs = g_h1r[1][(tn - 1) & 1] + moS; nwb = w3; }
                } else {
                    if (grp == 0) { nhs = g_h1r[0][tn & 1] + moS; nwb = w1; }
                    // grp1 odd next = cell10: no early operand
                }
            }
            if (nhs) {
                const float4* wl = nwb + wn4 * 256 + lane;
                if (tid == 0) issue_half(sb, mb0, 4, nhs);
                half_gemm(acc, smc, mb0, mpar, 4, wl, wm, rb, q);
                have_early = true;
            } else {
                have_early = false;
            }
        }

        // ---- wait ----
        __syncthreads();
        if (tid == 0) {
            while (g_gen < (unsigned)(ph + 1)) { }
        }
        __syncthreads();
        __threadfence();
    }

    // final H1f / M1f
    for (long idx = (long)cta * NTHR + tid; idx < 2L * BB * HH; idx += (long)GRID * NTHR) {
        int b = (int)(idx >> 10), l = (int)((idx >> 9) & 1), j = (int)(idx & 511);
        out[O_H1F + idx] = __ldcg(&g_h1f[l][b * HH + j]);
        out[O_M1F + idx] = __ldcg(&g_m1[l][b * HH + j]);
    }
}

// ---------------- prep kernels ----------------
// W fp16 fragment order. Half index f bits (LSB up):
// hb(1) r(1) j(1) lane(5) ks(3) wn4(2) kc(3) n0b(5) cell(2)
__global__ void prep_wf(const float* __restrict__ Wih, const float* __restrict__ Whh) {
    long f = (long)blockIdx.x * blockDim.x + threadIdx.x;
    if (f >= 8388608L) return;
    int hb   = (int)(f & 1);
    int r    = (int)((f >> 1) & 1);
    int j    = (int)((f >> 2) & 1);
    int lane = (int)((f >> 3) & 31);
    int ks   = (int)((f >> 8) & 7);
    int wn4  = (int)((f >> 11) & 3);
    int kc   = (int)((f >> 13) & 7);
    int n0b  = (int)((f >> 16) & 31);
    int cell = (int)(f >> 21);
    int rb = lane >> 2, q = lane & 3;
    int row = n0b * 64 + wn4 * 16 + j * 8 + rb;      // gate-interleaved: row = 4*unit + gate
    int g = row & 3, uu = row >> 2;
    long srow = (long)cell * NGATE + g * HH + uu;
    int k = kc * 128 + ks * 16 + r * 8 + 2 * q + hb;  // original k index
    float v = (k < HH) ? Wih[srow * HH + k] : Whh[srow * HH + (k - HH)];
    g_Wf[f] = __float2half_rn(v);
}

// H0 [B][T][H] -> g_H0r [t][kc][m][144] fp16, pair-level FORWARD k-permute
__global__ void prep_x(const float* __restrict__ H0) {
    long i = (long)blockIdx.x * blockDim.x + threadIdx.x;
    if (i >= (long)BB * TT * HH) return;
    int h = (int)(i & 511);
    int t = (int)((i >> 9) & 255);
    int b = (int)(i >> 17);
    int kc = h >> 7, k2 = h & 127;
    int blk = k2 >> 4, kb = (k2 >> 1) & 7, hb = k2 & 1;
    int p = (kb < 4) ? (2 * kb) : (2 * (kb - 4) + 1);
    int col = blk * 16 + p * 2 + hb;
    g_H0r[((long)t * 4 + kc) * CH_HF + (long)b * RSH + col] = __float2half_rn(H0[i]);
}

__global__ void prep_misc(const float* __restrict__ bih, const float* __restrict__ bhh) {
    long i = (long)blockIdx.x * blockDim.x + threadIdx.x;
    if (i < 147456) ((int*)g_h1r)[i] = 0;                        // zero fp16 h1r slabs
    if (i < 2L * BB * HH) { ((float*)g_h1f)[i] = 0.f; ((float*)g_m1)[i] = 0.f; }
    if (i < 4 * NGATE) {
        int nr = (int)(i & 2047), cc = (int)(i >> 11);
        int g = nr & 3, j = nr >> 2;
        long s = (long)cc * NGATE + g * HH + j;
        ((float*)g_bias)[i] = bih[s] + bhh[s];
    }
    if (i == 0) { g_cnt = 0; g_gen = 0; }
}

// ---------------- launch ----------------
extern "C" void kernel_launch(void* const* d_in, const int* in_sizes, int n_in,
                              void* d_out, int out_size) {
    const float* H0  = (const float*)d_in[0];
    const float* Wih = (const float*)d_in[1];
    const float* Whh = (const float*)d_in[2];
    const float* bih = (const float*)d_in[3];
    const float* bhh = (const float*)d_in[4];
    float* out = (float*)d_out;

    prep_wf<<<32768, 256>>>(Wih, Whh);
    prep_x<<<65536, 256>>>(H0);
    prep_misc<<<1024, 256>>>(bih, bhh);

    cudaFuncSetAttribute(lstm_main, cudaFuncAttributeMaxDynamicSharedMemorySize, SMEMB);
    lstm_main<<<GRID, NTHR, SMEMB>>>(out);
}